// round 5
// baseline (speedup 1.0000x reference)
#include <cuda_runtime.h>
#include <cuda_bf16.h>
#include <cstddef>

// Problem constants
#define NB   16          // batch
#define CIN  256         // input channels
#define WD   128         // width = CIN/2
#define SP   4096        // spatial = 64*64
#define KSPLIT 8         // split-K factor for kv GEMM (4096/512)

// ---- scratch (device globals; no allocation allowed) ----
__device__ float g_theta[(size_t)NB * WD * SP];
__device__ float g_phi  [(size_t)NB * WD * SP];
__device__ float g_g    [(size_t)NB * WD * SP];
__device__ float g_kvp  [(size_t)NB * KSPLIT * WD * WD];
__device__ float g_kv   [(size_t)NB * WD * WD];
__device__ float g_y    [(size_t)NB * SP * WD];   // flat [n][s*128+d]

// ============================================================
// Kernel A: theta/phi/g = relu(bn(W @ x))   per batch, per proj
// GEMM: M=128 (channels), N=128-tile of S, K=256
// grid: (S/128, 3, NB), block 256, 8x8 microtile
// ============================================================
__global__ __launch_bounds__(256) void qkv_kernel(
    const float* __restrict__ x,
    const float* __restrict__ w0, const float* __restrict__ w1, const float* __restrict__ w2,
    const float* __restrict__ g1, const float* __restrict__ b1, const float* __restrict__ m1, const float* __restrict__ v1,
    const float* __restrict__ g2, const float* __restrict__ b2, const float* __restrict__ m2, const float* __restrict__ v2,
    const float* __restrict__ g3, const float* __restrict__ b3, const float* __restrict__ m3, const float* __restrict__ v3)
{
    const int proj = blockIdx.y;
    const int n    = blockIdx.z;
    const int s0   = blockIdx.x * 128;
    const int tid  = threadIdx.x;

    const float* w  = (proj == 0) ? w0 : (proj == 1) ? w1 : w2;
    const float* bg = (proj == 0) ? g1 : (proj == 1) ? g2 : g3;
    const float* bb = (proj == 0) ? b1 : (proj == 1) ? b2 : b3;
    const float* bm = (proj == 0) ? m1 : (proj == 1) ? m2 : m3;
    const float* bv = (proj == 0) ? v1 : (proj == 1) ? v2 : v3;
    float* outp = (proj == 0) ? g_theta : (proj == 1) ? g_phi : g_g;

    __shared__ float As[8][136];   // W tile transposed: As[k][m]
    __shared__ float Bs[8][128];   // x tile: Bs[k][s]

    const int tm = (tid >> 4) * 8;     // 0..120  (channel sub-tile)
    const int tn = (tid & 15) * 8;     // 0..120  (spatial sub-tile)

    // load indices
    const int lam = tid >> 1;          // 0..127
    const int lak = (tid & 1) * 4;     // 0 or 4
    const int lbk = tid >> 5;          // 0..7
    const int lbs = (tid & 31) * 4;    // 0..124

    float acc[8][8];
#pragma unroll
    for (int i = 0; i < 8; i++)
#pragma unroll
        for (int j = 0; j < 8; j++) acc[i][j] = 0.f;

    const float* xbase = x + (size_t)n * CIN * SP + s0;

    for (int kt = 0; kt < CIN; kt += 8) {
        float4 wv = *(const float4*)(w + lam * CIN + kt + lak);
        As[lak + 0][lam] = wv.x;
        As[lak + 1][lam] = wv.y;
        As[lak + 2][lam] = wv.z;
        As[lak + 3][lam] = wv.w;
        *(float4*)&Bs[lbk][lbs] = *(const float4*)(xbase + (size_t)(kt + lbk) * SP + lbs);
        __syncthreads();
#pragma unroll
        for (int k = 0; k < 8; k++) {
            float a[8], b[8];
#pragma unroll
            for (int i = 0; i < 8; i++) a[i] = As[k][tm + i];
#pragma unroll
            for (int j = 0; j < 8; j++) b[j] = Bs[k][tn + j];
#pragma unroll
            for (int i = 0; i < 8; i++)
#pragma unroll
                for (int j = 0; j < 8; j++) acc[i][j] = fmaf(a[i], b[j], acc[i][j]);
        }
        __syncthreads();
    }

    float* obase = outp + (size_t)n * WD * SP + s0 + tn;
#pragma unroll
    for (int i = 0; i < 8; i++) {
        const int ch = tm + i;
        const float sc = bg[ch] * rsqrtf(bv[ch] + 1e-5f);
        const float sh = bb[ch] - bm[ch] * sc;
        float4 r0, r1;
        r0.x = fmaxf(fmaf(acc[i][0], sc, sh), 0.f);
        r0.y = fmaxf(fmaf(acc[i][1], sc, sh), 0.f);
        r0.z = fmaxf(fmaf(acc[i][2], sc, sh), 0.f);
        r0.w = fmaxf(fmaf(acc[i][3], sc, sh), 0.f);
        r1.x = fmaxf(fmaf(acc[i][4], sc, sh), 0.f);
        r1.y = fmaxf(fmaf(acc[i][5], sc, sh), 0.f);
        r1.z = fmaxf(fmaf(acc[i][6], sc, sh), 0.f);
        r1.w = fmaxf(fmaf(acc[i][7], sc, sh), 0.f);
        *(float4*)(obase + (size_t)ch * SP)     = r0;
        *(float4*)(obase + (size_t)ch * SP + 4) = r1;
    }
}

// ============================================================
// Kernel B: kv partials.  kvp[n][split][c][d] = sum_{s in chunk} phi[c][s]*g[d][s]
// M=N=128 (one tile), K-chunk=512. grid (KSPLIT, NB)
// ============================================================
__global__ __launch_bounds__(256) void kv_kernel()
{
    const int split = blockIdx.x;
    const int n     = blockIdx.y;
    const int s0    = split * (SP / KSPLIT);
    const int tid   = threadIdx.x;

    __shared__ float As[8][136];   // phi transposed: As[k(s)][c]
    __shared__ float Bs[8][136];   // g   transposed: Bs[k(s)][d]

    const int tm = (tid >> 4) * 8;
    const int tn = (tid & 15) * 8;
    const int lr = tid >> 1;           // row (c or d) 0..127
    const int lk = (tid & 1) * 4;      // k offset 0 or 4

    const float* pbase = g_phi + ((size_t)n * WD + lr) * SP + s0;
    const float* gbase = g_g   + ((size_t)n * WD + lr) * SP + s0;

    float acc[8][8];
#pragma unroll
    for (int i = 0; i < 8; i++)
#pragma unroll
        for (int j = 0; j < 8; j++) acc[i][j] = 0.f;

    for (int kt = 0; kt < SP / KSPLIT; kt += 8) {
        float4 pv = *(const float4*)(pbase + kt + lk);
        float4 gv = *(const float4*)(gbase + kt + lk);
        As[lk + 0][lr] = pv.x; As[lk + 1][lr] = pv.y; As[lk + 2][lr] = pv.z; As[lk + 3][lr] = pv.w;
        Bs[lk + 0][lr] = gv.x; Bs[lk + 1][lr] = gv.y; Bs[lk + 2][lr] = gv.z; Bs[lk + 3][lr] = gv.w;
        __syncthreads();
#pragma unroll
        for (int k = 0; k < 8; k++) {
            float a[8], b[8];
#pragma unroll
            for (int i = 0; i < 8; i++) a[i] = As[k][tm + i];
#pragma unroll
            for (int j = 0; j < 8; j++) b[j] = Bs[k][tn + j];
#pragma unroll
            for (int i = 0; i < 8; i++)
#pragma unroll
                for (int j = 0; j < 8; j++) acc[i][j] = fmaf(a[i], b[j], acc[i][j]);
        }
        __syncthreads();
    }

    float* obase = g_kvp + (((size_t)n * KSPLIT + split) * WD) * WD;
#pragma unroll
    for (int i = 0; i < 8; i++) {
        *(float4*)(obase + (size_t)(tm + i) * WD + tn)     = *(float4*)&acc[i][0];
        *(float4*)(obase + (size_t)(tm + i) * WD + tn + 4) = *(float4*)&acc[i][4];
    }
}

// reduce split-K partials
__global__ __launch_bounds__(256) void kv_reduce()
{
    const int idx = blockIdx.x * 256 + threadIdx.x;   // 0 .. NB*128*128-1
    const int n  = idx >> 14;
    const int cd = idx & 16383;
    float s = 0.f;
#pragma unroll
    for (int k = 0; k < KSPLIT; k++)
        s += g_kvp[((size_t)n * KSPLIT + k) * 16384 + cd];
    g_kv[idx] = s;
}

// ============================================================
// Kernel C: out_flat[n][s*128+d] = sum_c theta[n][c][s] * kv[n][c][d]
// M=128-tile of S, N=128 (d, whole), K=128 (c). grid (S/128, NB)
// ============================================================
__global__ __launch_bounds__(256) void outc_kernel()
{
    const int n   = blockIdx.y;
    const int s0  = blockIdx.x * 128;
    const int tid = threadIdx.x;

    __shared__ float As[8][128];   // theta: As[k(c)][s]  (direct)
    __shared__ float Bs[8][128];   // kv:    Bs[k(c)][d]  (direct)

    const int tm = (tid >> 4) * 8;     // s sub-tile
    const int tn = (tid & 15) * 8;     // d sub-tile
    const int lk = tid >> 5;           // 0..7
    const int lq = (tid & 31) * 4;     // 0..124

    const float* tbase = g_theta + (size_t)n * WD * SP + s0;
    const float* kbase = g_kv    + (size_t)n * WD * WD;

    float acc[8][8];
#pragma unroll
    for (int i = 0; i < 8; i++)
#pragma unroll
        for (int j = 0; j < 8; j++) acc[i][j] = 0.f;

    for (int c0 = 0; c0 < WD; c0 += 8) {
        *(float4*)&As[lk][lq] = *(const float4*)(tbase + (size_t)(c0 + lk) * SP + lq);
        *(float4*)&Bs[lk][lq] = *(const float4*)(kbase + (size_t)(c0 + lk) * WD + lq);
        __syncthreads();
#pragma unroll
        for (int k = 0; k < 8; k++) {
            float a[8], b[8];
#pragma unroll
            for (int i = 0; i < 8; i++) a[i] = As[k][tm + i];
#pragma unroll
            for (int j = 0; j < 8; j++) b[j] = Bs[k][tn + j];
#pragma unroll
            for (int i = 0; i < 8; i++)
#pragma unroll
                for (int j = 0; j < 8; j++) acc[i][j] = fmaf(a[i], b[j], acc[i][j]);
        }
        __syncthreads();
    }

    float* obase = g_y + (size_t)n * SP * WD + (size_t)s0 * WD + tn;
#pragma unroll
    for (int i = 0; i < 8; i++) {
        *(float4*)(obase + (size_t)(tm + i) * WD)     = *(float4*)&acc[i][0];
        *(float4*)(obase + (size_t)(tm + i) * WD + 4) = *(float4*)&acc[i][4];
    }
}

// ============================================================
// Kernel D: z = relu(bn4(w_zeta @ y) + x)
// y[n][w][s] = g_y flat at w*4096+s (the "reshape"). M=256 (o), N=S, K=128 (w)
// grid (S/128, 2, NB)
// ============================================================
__global__ __launch_bounds__(256) void zeta_kernel(
    const float* __restrict__ x, const float* __restrict__ wz,
    const float* __restrict__ g4, const float* __restrict__ b4,
    const float* __restrict__ m4, const float* __restrict__ v4,
    float* __restrict__ out)
{
    const int n   = blockIdx.z;
    const int o0  = blockIdx.y * 128;
    const int s0  = blockIdx.x * 128;
    const int tid = threadIdx.x;

    __shared__ float As[8][136];   // wz transposed: As[k(w)][o]
    __shared__ float Bs[8][128];   // y: Bs[k(w)][s]

    const int tm = (tid >> 4) * 8;     // o sub-tile
    const int tn = (tid & 15) * 8;     // s sub-tile
    const int lam = tid >> 1;
    const int lak = (tid & 1) * 4;
    const int lbk = tid >> 5;
    const int lbs = (tid & 31) * 4;

    const float* ybase = g_y + (size_t)n * SP * WD + s0;   // read as [w][s]: w*SP + s

    float acc[8][8];
#pragma unroll
    for (int i = 0; i < 8; i++)
#pragma unroll
        for (int j = 0; j < 8; j++) acc[i][j] = 0.f;

    for (int k0 = 0; k0 < WD; k0 += 8) {
        float4 wv = *(const float4*)(wz + (size_t)(o0 + lam) * WD + k0 + lak);
        As[lak + 0][lam] = wv.x;
        As[lak + 1][lam] = wv.y;
        As[lak + 2][lam] = wv.z;
        As[lak + 3][lam] = wv.w;
        *(float4*)&Bs[lbk][lbs] = *(const float4*)(ybase + (size_t)(k0 + lbk) * SP + lbs);
        __syncthreads();
#pragma unroll
        for (int k = 0; k < 8; k++) {
            float a[8], b[8];
#pragma unroll
            for (int i = 0; i < 8; i++) a[i] = As[k][tm + i];
#pragma unroll
            for (int j = 0; j < 8; j++) b[j] = Bs[k][tn + j];
#pragma unroll
            for (int i = 0; i < 8; i++)
#pragma unroll
                for (int j = 0; j < 8; j++) acc[i][j] = fmaf(a[i], b[j], acc[i][j]);
        }
        __syncthreads();
    }

    const float* xbase = x   + (size_t)n * CIN * SP + s0 + tn;
    float*       obase = out + (size_t)n * CIN * SP + s0 + tn;
#pragma unroll
    for (int i = 0; i < 8; i++) {
        const int ch = o0 + tm + i;
        const float sc = g4[ch] * rsqrtf(v4[ch] + 1e-5f);
        const float sh = b4[ch] - m4[ch] * sc;
        float4 x0 = *(const float4*)(xbase + (size_t)ch * SP);
        float4 x1 = *(const float4*)(xbase + (size_t)ch * SP + 4);
        float4 r0, r1;
        r0.x = fmaxf(fmaf(acc[i][0], sc, sh) + x0.x, 0.f);
        r0.y = fmaxf(fmaf(acc[i][1], sc, sh) + x0.y, 0.f);
        r0.z = fmaxf(fmaf(acc[i][2], sc, sh) + x0.z, 0.f);
        r0.w = fmaxf(fmaf(acc[i][3], sc, sh) + x0.w, 0.f);
        r1.x = fmaxf(fmaf(acc[i][4], sc, sh) + x1.x, 0.f);
        r1.y = fmaxf(fmaf(acc[i][5], sc, sh) + x1.y, 0.f);
        r1.z = fmaxf(fmaf(acc[i][6], sc, sh) + x1.z, 0.f);
        r1.w = fmaxf(fmaf(acc[i][7], sc, sh) + x1.w, 0.f);
        *(float4*)(obase + (size_t)ch * SP)     = r0;
        *(float4*)(obase + (size_t)ch * SP + 4) = r1;
    }
}

// ============================================================
extern "C" void kernel_launch(void* const* d_in, const int* in_sizes, int n_in,
                              void* d_out, int out_size)
{
    const float* x       = (const float*)d_in[0];
    const float* w_theta = (const float*)d_in[1];
    const float* w_phi   = (const float*)d_in[2];
    const float* w_g     = (const float*)d_in[3];
    const float* w_zeta  = (const float*)d_in[4];
    const float* bn1g = (const float*)d_in[5],  *bn1b = (const float*)d_in[6],
               * bn1m = (const float*)d_in[7],  *bn1v = (const float*)d_in[8];
    const float* bn2g = (const float*)d_in[9],  *bn2b = (const float*)d_in[10],
               * bn2m = (const float*)d_in[11], *bn2v = (const float*)d_in[12];
    const float* bn3g = (const float*)d_in[13], *bn3b = (const float*)d_in[14],
               * bn3m = (const float*)d_in[15], *bn3v = (const float*)d_in[16];
    const float* bn4g = (const float*)d_in[17], *bn4b = (const float*)d_in[18],
               * bn4m = (const float*)d_in[19], *bn4v = (const float*)d_in[20];
    float* out = (float*)d_out;

    dim3 gA(SP / 128, 3, NB);
    qkv_kernel<<<gA, 256>>>(x, w_theta, w_phi, w_g,
                            bn1g, bn1b, bn1m, bn1v,
                            bn2g, bn2b, bn2m, bn2v,
                            bn3g, bn3b, bn3m, bn3v);

    dim3 gB(KSPLIT, NB);
    kv_kernel<<<gB, 256>>>();

    kv_reduce<<<(NB * WD * WD) / 256, 256>>>();

    dim3 gC(SP / 128, NB);
    outc_kernel<<<gC, 256>>>();

    dim3 gD(SP / 128, CIN / 128, NB);
    zeta_kernel<<<gD, 256>>>(x, w_zeta, bn4g, bn4b, bn4m, bn4v, out);
}

// round 10
// speedup vs baseline: 2.0774x; 2.0774x over previous
#include <cuda_runtime.h>
#include <cuda_bf16.h>
#include <cstdint>
#include <cstddef>

#define NB   16
#define CIN  256
#define WD   128
#define SP   4096
#define KVS  32
#define EPSN 1e-5f
#define KC   32     // k-chunk in floats
#define ROWW 36     // SMEM words per row: 16 hi + 16 lo + 4 pad (stride%32=4 -> conflict-free frags)

// ---------------- scratch ----------------
__device__ float g_xT    [(size_t)NB * SP * CIN];
__device__ float g_thetaT[(size_t)NB * SP * WD];
__device__ float g_phi   [(size_t)NB * WD * SP];
__device__ float g_gm    [(size_t)NB * WD * SP];
__device__ float g_kvp   [(size_t)NB * KVS * WD * WD];
__device__ float g_kvT   [(size_t)NB * WD * WD];
__device__ float g_y     [(size_t)NB * SP * WD];
__device__ float g_yT    [(size_t)NB * SP * WD];

#define MMA_BF16(d, a0,a1,a2,a3, b0,b1) \
    asm volatile("mma.sync.aligned.m16n8k16.row.col.f32.bf16.bf16.f32 " \
        "{%0,%1,%2,%3}, {%4,%5,%6,%7}, {%8,%9}, {%0,%1,%2,%3};" \
        : "+f"((d)[0]), "+f"((d)[1]), "+f"((d)[2]), "+f"((d)[3]) \
        : "r"(a0), "r"(a1), "r"(a2), "r"(a3), "r"(b0), "r"(b1))

__device__ __forceinline__ void cvt_hl(float a, float b, uint32_t& hi, uint32_t& lo) {
    __nv_bfloat16 ha = __float2bfloat16_rn(a), hb = __float2bfloat16_rn(b);
    float fa = __bfloat162float(ha), fb = __bfloat162float(hb);
    __nv_bfloat16 la = __float2bfloat16_rn(a - fa), lb = __float2bfloat16_rn(b - fb);
    __nv_bfloat162 h; h.x = ha; h.y = hb;
    __nv_bfloat162 l; l.x = la; l.y = lb;
    hi = *reinterpret_cast<uint32_t*>(&h);
    lo = *reinterpret_cast<uint32_t*>(&l);
}

// load 128 rows x 32 floats from gmem (row stride ldk), split hi/lo bf16 into SMEM tile
__device__ __forceinline__ void load_conv(uint32_t* sm, const float* __restrict__ src,
                                          int ldk, int tid) {
#pragma unroll
    for (int i = 0; i < 4; i++) {
        int f = tid + (i << 8);          // 0..1023
        int row = f >> 3, c = f & 7;     // 8 float4 per row
        float4 v = *(const float4*)(src + (size_t)row * ldk + (c << 2));
        uint32_t h0, l0, h1, l1;
        cvt_hl(v.x, v.y, h0, l0);
        cvt_hl(v.z, v.w, h1, l1);
        uint32_t* p = sm + row * ROWW + c * 2;
        p[0] = h0; p[1] = h1;            // hi words 0..15
        p[16] = l0; p[17] = l1;          // lo words 16..31
    }
}

// D[128][128] = A[128][K] . B[128][K]^T with 3-product bf16 error compensation.
// acc[mi][ni][4] fragment layout: rows wr*64+mi*16+{r, r+8}, cols wc*32+ni*8+q*2+{0,1}
__device__ __forceinline__ void gemm_main(const float* __restrict__ A, int lda,
                                          const float* __restrict__ B, int ldb,
                                          int nchunk, float acc[4][4][4]) {
    __shared__ uint32_t smA[128 * ROWW];
    __shared__ uint32_t smB[128 * ROWW];
    const int tid = threadIdx.x, lane = tid & 31, wid = tid >> 5;
    const int wr = wid >> 2, wc = wid & 3;
    const int r = lane >> 2, q = lane & 3;
#pragma unroll
    for (int mi = 0; mi < 4; mi++)
#pragma unroll
        for (int ni = 0; ni < 4; ni++)
#pragma unroll
            for (int k = 0; k < 4; k++) acc[mi][ni][k] = 0.f;

    for (int kc = 0; kc < nchunk; kc++) {
        load_conv(smA, A + kc * KC, lda, tid);
        load_conv(smB, B + kc * KC, ldb, tid);
        __syncthreads();
        // passes: (Ah,Bh), (Al,Bh), (Ah,Bl); each = 2 k-steps of 16 bf16
#pragma unroll
        for (int p = 0; p < 3; p++) {
            const int aoff = (p == 1) ? 16 : 0;
            const int boff = (p == 2) ? 16 : 0;
#pragma unroll
            for (int k2 = 0; k2 < 2; k2++) {
                const int kwA = aoff + k2 * 8, kwB = boff + k2 * 8;
                uint32_t bf[4][2];
#pragma unroll
                for (int ni = 0; ni < 4; ni++) {
                    int nr = wc * 32 + ni * 8 + r;
                    bf[ni][0] = smB[nr * ROWW + kwB + q];
                    bf[ni][1] = smB[nr * ROWW + kwB + 4 + q];
                }
#pragma unroll
                for (int mi = 0; mi < 4; mi++) {
                    int mr = wr * 64 + mi * 16 + r;
                    uint32_t a0 = smA[mr * ROWW + kwA + q];
                    uint32_t a1 = smA[(mr + 8) * ROWW + kwA + q];
                    uint32_t a2 = smA[mr * ROWW + kwA + 4 + q];
                    uint32_t a3 = smA[(mr + 8) * ROWW + kwA + 4 + q];
#pragma unroll
                    for (int ni = 0; ni < 4; ni++)
                        MMA_BF16(acc[mi][ni], a0, a1, a2, a3, bf[ni][0], bf[ni][1]);
                }
            }
        }
        __syncthreads();
    }
}

// ---------------- transposes ----------------
__global__ __launch_bounds__(256) void transpose_x_k(const float* __restrict__ x) {
    __shared__ float t[32][33];
    int n = blockIdx.z, c0 = blockIdx.x * 32, r0 = blockIdx.y * 32;
    int tx = threadIdx.x, ty = threadIdx.y;
    const float* ib = x + (size_t)n * CIN * SP;
    float* ob = g_xT + (size_t)n * SP * CIN;
#pragma unroll
    for (int i = 0; i < 32; i += 8) t[ty + i][tx] = ib[(size_t)(r0 + ty + i) * SP + c0 + tx];
    __syncthreads();
#pragma unroll
    for (int i = 0; i < 32; i += 8) ob[(size_t)(c0 + ty + i) * CIN + r0 + tx] = t[tx][ty + i];
}
__global__ __launch_bounds__(256) void transpose_y_k() {
    __shared__ float t[32][33];
    int n = blockIdx.z, c0 = blockIdx.x * 32, r0 = blockIdx.y * 32;
    int tx = threadIdx.x, ty = threadIdx.y;
    const float* ib = g_y + (size_t)n * WD * SP;
    float* ob = g_yT + (size_t)n * SP * WD;
#pragma unroll
    for (int i = 0; i < 32; i += 8) t[ty + i][tx] = ib[(size_t)(r0 + ty + i) * SP + c0 + tx];
    __syncthreads();
#pragma unroll
    for (int i = 0; i < 32; i += 8) ob[(size_t)(c0 + ty + i) * WD + r0 + tx] = t[tx][ty + i];
}

// ---------------- GEMM 1: theta/phi/g ----------------
// grid (3, SP/128, NB): proj fastest -> xT tile L2 reuse across projs
__global__ __launch_bounds__(256, 2) void qkv_tc(
    const float* __restrict__ w0, const float* __restrict__ w1, const float* __restrict__ w2,
    const float* __restrict__ g1, const float* __restrict__ b1, const float* __restrict__ m1, const float* __restrict__ v1,
    const float* __restrict__ g2, const float* __restrict__ b2, const float* __restrict__ m2, const float* __restrict__ v2,
    const float* __restrict__ g3, const float* __restrict__ b3, const float* __restrict__ m3, const float* __restrict__ v3)
{
    const int proj = blockIdx.x, n = blockIdx.z, s0 = blockIdx.y * 128;
    const float* w = (proj == 0) ? w0 : (proj == 1) ? w1 : w2;
    const float* xsrc = g_xT + ((size_t)n * SP + s0) * CIN;
    float acc[4][4][4];
    if (proj == 0) gemm_main(xsrc, CIN, w, CIN, CIN / KC, acc);  // D[s][c']
    else           gemm_main(w, CIN, xsrc, CIN, CIN / KC, acc);  // D[c'][s]

    const int lane = threadIdx.x & 31, wid = threadIdx.x >> 5;
    const int wr = wid >> 2, wc = wid & 3, r = lane >> 2, q = lane & 3;

    if (proj == 0) {    // BN per column c'
#pragma unroll
        for (int mi = 0; mi < 4; mi++) {
            int sr = wr * 64 + mi * 16 + r;
            float* d0 = g_thetaT + ((size_t)n * SP + s0 + sr) * WD;
            float* d1 = d0 + (size_t)8 * WD;
#pragma unroll
            for (int ni = 0; ni < 4; ni++) {
                int col = wc * 32 + ni * 8 + q * 2;
                float sa = g1[col] * rsqrtf(v1[col] + EPSN);
                float ha = b1[col] - m1[col] * sa;
                float sb = g1[col + 1] * rsqrtf(v1[col + 1] + EPSN);
                float hb = b1[col + 1] - m1[col + 1] * sb;
                float2 u, v2_;
                u.x   = fmaxf(fmaf(acc[mi][ni][0], sa, ha), 0.f);
                u.y   = fmaxf(fmaf(acc[mi][ni][1], sb, hb), 0.f);
                v2_.x = fmaxf(fmaf(acc[mi][ni][2], sa, ha), 0.f);
                v2_.y = fmaxf(fmaf(acc[mi][ni][3], sb, hb), 0.f);
                *(float2*)(d0 + col) = u;
                *(float2*)(d1 + col) = v2_;
            }
        }
    } else {            // BN per row c'
        const float* bg = (proj == 1) ? g2 : g3; const float* bb = (proj == 1) ? b2 : b3;
        const float* bm = (proj == 1) ? m2 : m3; const float* bv = (proj == 1) ? v2 : v3;
        float* dst = (proj == 1) ? g_phi : g_gm;
#pragma unroll
        for (int mi = 0; mi < 4; mi++) {
            int c0r = wr * 64 + mi * 16 + r, c1r = c0r + 8;
            float sA = bg[c0r] * rsqrtf(bv[c0r] + EPSN), hA = bb[c0r] - bm[c0r] * sA;
            float sB = bg[c1r] * rsqrtf(bv[c1r] + EPSN), hB = bb[c1r] - bm[c1r] * sB;
            float* p0 = dst + ((size_t)n * WD + c0r) * SP + s0;
            float* p1 = dst + ((size_t)n * WD + c1r) * SP + s0;
#pragma unroll
            for (int ni = 0; ni < 4; ni++) {
                int col = wc * 32 + ni * 8 + q * 2;
                float2 u, v2_;
                u.x   = fmaxf(fmaf(acc[mi][ni][0], sA, hA), 0.f);
                u.y   = fmaxf(fmaf(acc[mi][ni][1], sA, hA), 0.f);
                v2_.x = fmaxf(fmaf(acc[mi][ni][2], sB, hB), 0.f);
                v2_.y = fmaxf(fmaf(acc[mi][ni][3], sB, hB), 0.f);
                *(float2*)(p0 + col) = u;
                *(float2*)(p1 + col) = v2_;
            }
        }
    }
}

// ---------------- GEMM 2: kv partials (D[d][c]) ---------------- grid (KVS, NB)
__global__ __launch_bounds__(256, 2) void kv_tc()
{
    const int n = blockIdx.y, s0 = blockIdx.x * (SP / KVS);
    const float* gsrc = g_gm  + (size_t)n * WD * SP + s0;
    const float* psrc = g_phi + (size_t)n * WD * SP + s0;
    float acc[4][4][4];
    gemm_main(gsrc, SP, psrc, SP, (SP / KVS) / KC, acc);

    const int lane = threadIdx.x & 31, wid = threadIdx.x >> 5;
    const int wr = wid >> 2, wc = wid & 3, r = lane >> 2, q = lane & 3;
    float* base = g_kvp + ((size_t)n * KVS + blockIdx.x) * WD * WD;
#pragma unroll
    for (int mi = 0; mi < 4; mi++) {
        int dr = wr * 64 + mi * 16 + r;
        float* p0 = base + (size_t)dr * WD;
        float* p1 = p0 + (size_t)8 * WD;
#pragma unroll
        for (int ni = 0; ni < 4; ni++) {
            int col = wc * 32 + ni * 8 + q * 2;
            *(float2*)(p0 + col) = make_float2(acc[mi][ni][0], acc[mi][ni][1]);
            *(float2*)(p1 + col) = make_float2(acc[mi][ni][2], acc[mi][ni][3]);
        }
    }
}
__global__ __launch_bounds__(256) void kv_reduce()
{
    int idx = blockIdx.x * 256 + threadIdx.x;
    int n = idx >> 14, dc = idx & 16383;
    float s = 0.f;
#pragma unroll
    for (int k = 0; k < KVS; k++) s += g_kvp[(((size_t)n * KVS + k) << 14) + dc];
    g_kvT[idx] = s;
}

// ---------------- GEMM 3: y_flat (D[s][d]) ---------------- grid (SP/128, NB)
__global__ __launch_bounds__(256, 2) void outc_tc()
{
    const int n = blockIdx.y, s0 = blockIdx.x * 128;
    const float* tsrc = g_thetaT + ((size_t)n * SP + s0) * WD;
    const float* ksrc = g_kvT + (size_t)n * WD * WD;
    float acc[4][4][4];
    gemm_main(tsrc, WD, ksrc, WD, WD / KC, acc);

    const int lane = threadIdx.x & 31, wid = threadIdx.x >> 5;
    const int wr = wid >> 2, wc = wid & 3, r = lane >> 2, q = lane & 3;
#pragma unroll
    for (int mi = 0; mi < 4; mi++) {
        int sr = wr * 64 + mi * 16 + r;
        float* p0 = g_y + ((size_t)n * SP + s0 + sr) * WD;
        float* p1 = p0 + (size_t)8 * WD;
#pragma unroll
        for (int ni = 0; ni < 4; ni++) {
            int col = wc * 32 + ni * 8 + q * 2;
            *(float2*)(p0 + col) = make_float2(acc[mi][ni][0], acc[mi][ni][1]);
            *(float2*)(p1 + col) = make_float2(acc[mi][ni][2], acc[mi][ni][3]);
        }
    }
}

// ---------------- GEMM 4: zeta + BN4 + residual + relu (D[o][s]) ----------------
// grid (CIN/128, SP/128, NB): o-tile fastest -> yT tile L2 reuse
__global__ __launch_bounds__(256, 2) void zeta_tc(
    const float* __restrict__ x, const float* __restrict__ wz,
    const float* __restrict__ g4, const float* __restrict__ b4,
    const float* __restrict__ m4, const float* __restrict__ v4,
    float* __restrict__ out)
{
    const int n = blockIdx.z, o0 = blockIdx.x * 128, s0 = blockIdx.y * 128;
    const float* wsrc = wz + (size_t)o0 * WD;
    const float* ysrc = g_yT + ((size_t)n * SP + s0) * WD;
    float acc[4][4][4];
    gemm_main(wsrc, WD, ysrc, WD, WD / KC, acc);

    const int lane = threadIdx.x & 31, wid = threadIdx.x >> 5;
    const int wr = wid >> 2, wc = wid & 3, r = lane >> 2, q = lane & 3;
#pragma unroll
    for (int mi = 0; mi < 4; mi++) {
        int oA = o0 + wr * 64 + mi * 16 + r, oB = oA + 8;
        float sA = g4[oA] * rsqrtf(v4[oA] + EPSN), hA = b4[oA] - m4[oA] * sA;
        float sB = g4[oB] * rsqrtf(v4[oB] + EPSN), hB = b4[oB] - m4[oB] * sB;
        const float* x0 = x + ((size_t)n * CIN + oA) * SP + s0;
        const float* x1 = x + ((size_t)n * CIN + oB) * SP + s0;
        float* p0 = out + ((size_t)n * CIN + oA) * SP + s0;
        float* p1 = out + ((size_t)n * CIN + oB) * SP + s0;
#pragma unroll
        for (int ni = 0; ni < 4; ni++) {
            int col = wc * 32 + ni * 8 + q * 2;
            float2 xa = *(const float2*)(x0 + col);
            float2 xb = *(const float2*)(x1 + col);
            float2 u, v2_;
            u.x   = fmaxf(fmaf(acc[mi][ni][0], sA, hA) + xa.x, 0.f);
            u.y   = fmaxf(fmaf(acc[mi][ni][1], sA, hA) + xa.y, 0.f);
            v2_.x = fmaxf(fmaf(acc[mi][ni][2], sB, hB) + xb.x, 0.f);
            v2_.y = fmaxf(fmaf(acc[mi][ni][3], sB, hB) + xb.y, 0.f);
            *(float2*)(p0 + col) = u;
            *(float2*)(p1 + col) = v2_;
        }
    }
}

// ---------------- launcher ----------------
extern "C" void kernel_launch(void* const* d_in, const int* in_sizes, int n_in,
                              void* d_out, int out_size)
{
    const float* x  = (const float*)d_in[0];
    const float* wt = (const float*)d_in[1];
    const float* wp = (const float*)d_in[2];
    const float* wg = (const float*)d_in[3];
    const float* wz = (const float*)d_in[4];
    const float* p[16];
    for (int i = 0; i < 16; i++) p[i] = (const float*)d_in[5 + i];
    float* out = (float*)d_out;

    dim3 blkT(32, 8);
    transpose_x_k<<<dim3(SP / 32, CIN / 32, NB), blkT>>>(x);

    qkv_tc<<<dim3(3, SP / 128, NB), 256>>>(wt, wp, wg,
        p[0], p[1], p[2], p[3], p[4], p[5], p[6], p[7], p[8], p[9], p[10], p[11]);

    kv_tc<<<dim3(KVS, NB), 256>>>();
    kv_reduce<<<(NB * WD * WD) / 256, 256>>>();

    outc_tc<<<dim3(SP / 128, NB), 256>>>();

    transpose_y_k<<<dim3(SP / 32, WD / 32, NB), blkT>>>();

    zeta_tc<<<dim3(CIN / 128, SP / 128, NB), 256>>>(x, wz, p[12], p[13], p[14], p[15], out);
}